// round 16
// baseline (speedup 1.0000x reference)
#include <cuda_runtime.h>

#define N_PILLARS 30000
#define WPB 8
#define GRID_A 1184   // pass1
#define GRID_C 740    // pass3
#define NM_F 960000.0f
#define LOG2E 1.44269504088896340736f
#define NPART 62

__device__ float4 g_wk[N_PILLARS * 32];    // {wt, K0, K1, npf} per (pillar,lane)
__device__ float  g_part[GRID_A * NPART];  // per-block stat partials
__device__ float  g_ab[128];               // [0:64)=scale a, [64:128)=bias b

#define INFF __int_as_float(0x7f800000)

__device__ __forceinline__ float wredsum(float v) {
#pragma unroll
    for (int o = 16; o; o >>= 1) v += __shfl_xor_sync(0xffffffffu, v, o);
    return v;
}
__device__ __forceinline__ float wredmax(float v) {
#pragma unroll
    for (int o = 16; o; o >>= 1) v = fmaxf(v, __shfl_xor_sync(0xffffffffu, v, o));
    return v;
}
__device__ __forceinline__ float wredmin(float v) {
#pragma unroll
    for (int o = 16; o; o >>= 1) v = fminf(v, __shfl_xor_sync(0xffffffffu, v, o));
    return v;
}
__device__ __forceinline__ float ex2a(float x) {
    float r; asm("ex2.approx.f32 %0, %1;" : "=f"(r) : "f"(x)); return r;
}

// entry e -> stage-index triple (value = st[ia]*st[ib]*st[ic])
// stage: [0..2]=cx,cy,cz  [3..5]=mx,my,mz  [6..9]=Sx,Sy,Sz,Sw  [10]=npf  [11]=1
__device__ __forceinline__ void etriple(int e, int& ia, int& ib, int& ic) {
    if (e < 3)       { ia = e; ib = 10; ic = 11; }
    else if (e < 27) { int t = e - 3; ia = t >> 2; ib = 6 + (t & 3); ic = 11; }
    else {
        int t = e - 27; int a = 0;
        while (t >= 6 - a) { t -= 6 - a; a++; }
        ia = a; ib = a + t; ic = 10;
    }
}

// ---------------------------------------------------------------------------
// Pass 1: attention + K + npf -> g_wk (two STG.64 halves, R9 schedule);
// linearized BN stat accumulators.
// ---------------------------------------------------------------------------
__global__ __launch_bounds__(256) void pass1_kernel(
    const float4* __restrict__ feat,
    const int*    __restrict__ npts,
    const int4*   __restrict__ coors,
    const float*  __restrict__ W,
    const float*  __restrict__ wq, const float* __restrict__ wk,
    const float*  __restrict__ wv, const float* __restrict__ wo,
    const float*  __restrict__ bq, const float* __restrict__ bk,
    const float*  __restrict__ bv, const float* __restrict__ bo)
{
    __shared__ float  shw[48];
    __shared__ float4 sh_kva[WPB][32];   // {k0,v0,k1,v1}
    __shared__ float2 sh_kvb[WPB][32];   // {k2,v2}
    __shared__ float  sh_st[WPB][12];
    __shared__ float  sh_e[WPB][48];
    __shared__ float  sh_m[WPB][14];

    const int tid  = threadIdx.x;
    const int wid  = tid >> 5;
    const int lane = tid & 31;

    if (tid < 9) { shw[tid] = wq[tid]; shw[9 + tid] = wk[tid]; shw[18 + tid] = wv[tid]; shw[27 + tid] = wo[tid]; }
    if (tid < 3) { shw[36 + tid] = bq[tid]; shw[39 + tid] = bk[tid]; shw[42 + tid] = bv[tid]; shw[45 + tid] = bo[tid]; }
    __syncthreads();

    const int c0 = lane, c1 = lane + 32;
    const float P00 = W[c0] + W[448 + c0], P10 = W[64 + c0] + W[512 + c0], P20 = W[128 + c0] + W[576 + c0];
    const float Q00 = W[256 + c0], Q10 = W[320 + c0], Q20 = W[384 + c0];
    const float P01 = W[c1] + W[448 + c1], P11 = W[64 + c1] + W[512 + c1], P21 = W[128 + c1] + W[576 + c1];
    const float Q01 = W[256 + c1], Q11 = W[320 + c1], Q21 = W[384 + c1];

    int ia0, ib0, ic0, ia1, ib1, ic1;
    etriple(lane, ia0, ib0, ic0);
    const bool has1 = (lane < 16);
    etriple(has1 ? (32 + lane) : 0, ia1, ib1, ic1);

    float macc[10]; float sacc[4];
#pragma unroll
    for (int k = 0; k < 10; k++) macc[k] = 0.f;
#pragma unroll
    for (int k = 0; k < 4; k++) sacc[k] = 0.f;
    float ea0 = 0.f, ea1 = 0.f;

    for (int n = blockIdx.x * WPB + wid; n < N_PILLARS; n += GRID_A * WPB) {
        float4 f = feat[n * 32 + lane];
        int np = npts[n];
        int4 cc = coors[n];
        float cx = (float)cc.w * 0.2f + 0.1f;
        float cy = (float)cc.z * 0.2f - 39.9f;
        float cz = (float)cc.y * 4.0f - 1.0f;

        // ---- q,k,v ----
        float q0 = fmaf(f.x, shw[0], fmaf(f.y, shw[3], fmaf(f.z, shw[6], shw[36])));
        float q1 = fmaf(f.x, shw[1], fmaf(f.y, shw[4], fmaf(f.z, shw[7], shw[37])));
        float q2 = fmaf(f.x, shw[2], fmaf(f.y, shw[5], fmaf(f.z, shw[8], shw[38])));
        float k0 = fmaf(f.x, shw[9],  fmaf(f.y, shw[12], fmaf(f.z, shw[15], shw[39])));
        float k1 = fmaf(f.x, shw[10], fmaf(f.y, shw[13], fmaf(f.z, shw[16], shw[40])));
        float k2 = fmaf(f.x, shw[11], fmaf(f.y, shw[14], fmaf(f.z, shw[17], shw[41])));
        float v0 = fmaf(f.x, shw[18], fmaf(f.y, shw[21], fmaf(f.z, shw[24], shw[42])));
        float v1 = fmaf(f.x, shw[19], fmaf(f.y, shw[22], fmaf(f.z, shw[25], shw[43])));
        float v2 = fmaf(f.x, shw[20], fmaf(f.y, shw[23], fmaf(f.z, shw[26], shw[44])));
        float qs0 = q0 * LOG2E, qs1 = q1 * LOG2E, qs2 = q2 * LOG2E;

        // ---- stats reductions ----
        float Ux = wredsum(f.x), Uy = wredsum(f.y), Uz = wredsum(f.z);
        float npf = (float)np;
        float inv = __fdividef(1.0f, npf);
        float mx = Ux * inv, my = Uy * inv, mz = Uz * inv;

        bool val = (lane < np);
        float X = val ? f.x : 0.f, Y = val ? f.y : 0.f, Z = val ? f.z : 0.f, Wv = val ? f.w : 0.f;
        float Sx = wredsum(X), Sy = wredsum(Y), Sz = wredsum(Z), Sw = wredsum(Wv);

        macc[0] = fmaf(X, X, macc[0]); macc[1] = fmaf(X, Y, macc[1]);
        macc[2] = fmaf(X, Z, macc[2]); macc[3] = fmaf(X, Wv, macc[3]);
        macc[4] = fmaf(Y, Y, macc[4]); macc[5] = fmaf(Y, Z, macc[5]);
        macc[6] = fmaf(Y, Wv, macc[6]); macc[7] = fmaf(Z, Z, macc[7]);
        macc[8] = fmaf(Z, Wv, macc[8]); macc[9] = fmaf(Wv, Wv, macc[9]);
        sacc[0] += X; sacc[1] += Y; sacc[2] += Z; sacc[3] += Wv;

        float K0 = -fmaf(cx, P00, fmaf(cy, P10, fmaf(cz, P20, fmaf(mx, Q00, fmaf(my, Q10, mz * Q20)))));
        float K1 = -fmaf(cx, P01, fmaf(cy, P11, fmaf(cz, P21, fmaf(mx, Q01, fmaf(my, Q11, mz * Q21)))));

        // early half-store: {K1, npf} -> g_wk[].zw  (dies immediately, like R9's g_k store)
        float2* wkp = reinterpret_cast<float2*>(&g_wk[n * 32 + lane]);
        wkp[1] = make_float2(K1, npf);

        // ---- stage smem ----
        __syncwarp();
        sh_kva[wid][lane] = make_float4(k0, v0, k1, v1);
        sh_kvb[wid][lane] = make_float2(k2, v2);
        if (lane == 0) {
            float* st = sh_st[wid];
            st[0] = cx; st[1] = cy; st[2] = cz;
            st[3] = mx; st[4] = my; st[5] = mz;
            st[6] = Sx; st[7] = Sy; st[8] = Sz; st[9] = Sw;
            st[10] = npf; st[11] = 1.0f;
        }
        __syncwarp();

        const float* st = sh_st[wid];
        ea0 = fmaf(st[ia0] * st[ib0], st[ic0], ea0);
        if (has1) ea1 = fmaf(st[ia1] * st[ib1], st[ic1], ea1);

        // ---- exp loop (fully unrolled) ----
        float l0 = 0.f, l1 = 0.f, l2 = 0.f, a0 = 0.f, a1 = 0.f, a2 = 0.f;
#pragma unroll
        for (int j = 0; j < 32; j++) {
            float4 kva = sh_kva[wid][j];
            float2 kvb = sh_kvb[wid][j];
            float e0 = ex2a(qs0 * kva.x);
            float e1 = ex2a(qs1 * kva.z);
            float e2 = ex2a(qs2 * kvb.x);
            l0 += e0; l1 += e1; l2 += e2;
            a0 = fmaf(e0, kva.y, a0);
            a1 = fmaf(e1, kva.w, a1);
            a2 = fmaf(e2, kvb.y, a2);
        }
        float o0 = __fdividef(a0, l0);
        float o1 = __fdividef(a1, l1);
        float o2 = __fdividef(a2, l2);
        float t0 = fmaf(o0, shw[27], fmaf(o1, shw[30], fmaf(o2, shw[33], shw[45])));
        float t1 = fmaf(o0, shw[28], fmaf(o1, shw[31], fmaf(o2, shw[34], shw[46])));
        float t2 = fmaf(o0, shw[29], fmaf(o1, shw[32], fmaf(o2, shw[35], shw[47])));
        float ma = fmaxf(t0, fmaxf(t1, t2));
        float S = wredsum(ma);
        float wt = __fdividef(ma, S);

        // late half-store: {wt, K0} -> g_wk[].xy  (K0 carried through exp loop: +1 reg)
        wkp[0] = make_float2(wt, K0);
    }

    // block reduction of stats
    sh_e[wid][lane] = ea0;
    if (has1) sh_e[wid][32 + lane] = ea1;
#pragma unroll
    for (int k = 0; k < 10; k++) macc[k] = wredsum(macc[k]);
#pragma unroll
    for (int k = 0; k < 4; k++) sacc[k] = wredsum(sacc[k]);
    if (lane == 0) {
#pragma unroll
        for (int k = 0; k < 10; k++) sh_m[wid][k] = macc[k];
#pragma unroll
        for (int k = 0; k < 4; k++) sh_m[wid][10 + k] = sacc[k];
    }
    __syncthreads();
    if (tid < 48) {
        float s = 0.f;
#pragma unroll
        for (int w = 0; w < WPB; w++) s += sh_e[w][tid];
        g_part[blockIdx.x * NPART + tid] = s;
    } else if (tid < NPART) {
        float s = 0.f;
#pragma unroll
        for (int w = 0; w < WPB; w++) s += sh_m[w][tid - 48];
        g_part[blockIdx.x * NPART + tid] = s;
    }
}

// ---------------------------------------------------------------------------
// Pass 2: contract global stats per channel -> BN scale/bias
// ---------------------------------------------------------------------------
__global__ __launch_bounds__(1024) void pass2_kernel(
    const float* __restrict__ W,
    const float* __restrict__ gamma, const float* __restrict__ beta)
{
    __shared__ float shv[64][16];
    __shared__ float tot[NPART];
    int tid = threadIdx.x;
    int v = tid & 63, grp = tid >> 6;
    if (v < NPART) {
        float s = 0.f;
#pragma unroll 8
        for (int b = grp; b < GRID_A; b += 16) s += g_part[b * NPART + v];
        shv[v][grp] = s;
    }
    __syncthreads();
    if (tid < NPART) {
        float s = 0.f;
#pragma unroll
        for (int g = 0; g < 16; g++) s += shv[tid][g];
        tot[tid] = s;
    }
    __syncthreads();
    if (tid < 64) {
        int c = tid;
        float P0 = W[c] + W[448 + c], P1 = W[64 + c] + W[512 + c], P2 = W[128 + c] + W[576 + c];
        float Q0 = W[256 + c], Q1 = W[320 + c], Q2 = W[384 + c];
        float A[4] = { P0 + Q0, P1 + Q1, P2 + Q2, W[192 + c] };
        float R[6] = { P0, P1, P2, Q0, Q1, Q2 };
        float SG[4] = { tot[58], tot[59], tot[60], tot[61] };
        float T1[6] = { tot[0], tot[1], tot[2], tot[58], tot[59], tot[60] };

        float rs = A[0]*SG[0] + A[1]*SG[1] + A[2]*SG[2] + A[3]*SG[3]
                 - (R[0]*T1[0] + R[1]*T1[1] + R[2]*T1[2] + R[3]*T1[3] + R[4]*T1[4] + R[5]*T1[5]);

        float M[4][4];
        M[0][0]=tot[48]; M[0][1]=M[1][0]=tot[49]; M[0][2]=M[2][0]=tot[50]; M[0][3]=M[3][0]=tot[51];
        M[1][1]=tot[52]; M[1][2]=M[2][1]=tot[53]; M[1][3]=M[3][1]=tot[54];
        M[2][2]=tot[55]; M[2][3]=M[3][2]=tot[56]; M[3][3]=tot[57];
        float quadA = 0.f;
#pragma unroll
        for (int a = 0; a < 4; a++) {
            float h = 0.f;
#pragma unroll
            for (int b = 0; b < 4; b++) h += M[a][b] * A[b];
            quadA += A[a] * h;
        }
        float cross = 0.f;
#pragma unroll
        for (int b = 0; b < 4; b++) {
            float vb = 0.f;
#pragma unroll
            for (int a = 0; a < 6; a++) vb += R[a] * tot[3 + a * 4 + b];
            cross += vb * A[b];
        }
        float T3[6][6];
        int idx = 27;
#pragma unroll
        for (int a = 0; a < 6; a++)
#pragma unroll
            for (int b = a; b < 6; b++) { T3[a][b] = T3[b][a] = tot[idx]; idx++; }
        float quadR = 0.f;
#pragma unroll
        for (int a = 0; a < 6; a++) {
            float h = 0.f;
#pragma unroll
            for (int b = 0; b < 6; b++) h += T3[a][b] * R[b];
            quadR += R[a] * h;
        }
        float rq = quadA - 2.0f * cross + quadR;
        float mean = rs * (1.0f / NM_F);
        float var  = rq * (1.0f / NM_F) - mean * mean;
        float a = gamma[c] * rsqrtf(var + 1e-3f);
        g_ab[c] = a;
        g_ab[64 + c] = fmaf(-mean, a, beta[c]);
    }
}

// ---------------------------------------------------------------------------
// Pass 3: only TWO global loads per pillar (feat + g_wk).
// BN folded into coefficients; software-pipelined.  (R15-measured ~19.6us)
// ---------------------------------------------------------------------------
__global__ __launch_bounds__(256) void pass3_kernel(
    const float4* __restrict__ feat,
    const float*  __restrict__ W,
    float*        __restrict__ out)
{
    __shared__ float4 sh_p[WPB][32];
    __shared__ float  sh_wt[WPB][32];

    const int tid  = threadIdx.x;
    const int wid  = tid >> 5;
    const int lane = tid & 31;
    const int c0 = lane, c1 = lane + 32;

    const float sa0 = g_ab[c0], sb0 = g_ab[64 + c0];
    const float sa1 = g_ab[c1], sb1 = g_ab[64 + c1];

    const float B00 = sa0 * (W[c0] + W[448 + c0] + W[256 + c0]);
    const float B10 = sa0 * (W[64 + c0] + W[512 + c0] + W[320 + c0]);
    const float B20 = sa0 * (W[128 + c0] + W[576 + c0] + W[384 + c0]);
    const float b30 = sa0 * W[192 + c0];
    const float B01 = sa1 * (W[c1] + W[448 + c1] + W[256 + c1]);
    const float B11 = sa1 * (W[64 + c1] + W[512 + c1] + W[320 + c1]);
    const float B21 = sa1 * (W[128 + c1] + W[576 + c1] + W[384 + c1]);
    const float b31 = sa1 * W[192 + c1];

    const float ym0 = fmaxf(sb0, 0.01f * sb0);
    const float ym1 = fmaxf(sb1, 0.01f * sb1);

    const int stride = GRID_C * WPB;
    int n = blockIdx.x * WPB + wid;

    float4 f;  float4 wk;
    if (n < N_PILLARS) {
        f  = feat[n * 32 + lane];
        wk = g_wk[n * 32 + lane];
    }

    while (n < N_PILLARS) {
        const int n2 = n + stride;
        float4 f2; float4 wk2;
        if (n2 < N_PILLARS) {   // prefetch next pillar (2 independent streams)
            f2  = feat[n2 * 32 + lane];
            wk2 = g_wk[n2 * 32 + lane];
        }

        const float wt = wk.x;
        const int   np = (int)wk.w;

        __syncwarp();
        sh_p[wid][lane]  = f;
        sh_wt[wid][lane] = wt;
        __syncwarp();

        float wmx = wredmax((lane >= np) ? wt : -INFF);
        float wmn = wredmin((lane >= np) ? wt :  INFF);

        const float Kb0 = fmaf(sa0, wk.y, sb0);
        const float Kb1 = fmaf(sa1, wk.z, sb1);

        float fm0 = -INFF, fa0 = -INFF, fm1 = -INFF, fa1 = -INFF;
        if (np < 32) {
            fm0 = ym0;  fa0 = (ym0 >= 0.f) ? ym0 * wmx : ym0 * wmn;
            fm1 = ym1;  fa1 = (ym1 >= 0.f) ? ym1 * wmx : ym1 * wmn;
        }
#pragma unroll 4
        for (int i = 0; i < np; i++) {
            float4 p = sh_p[wid][i];
            float w  = sh_wt[wid][i];
            float y0 = fmaf(p.x, B00, fmaf(p.y, B10, fmaf(p.z, B20, fmaf(p.w, b30, Kb0))));
            y0 = fmaxf(y0, 0.01f * y0);
            fm0 = fmaxf(fm0, y0);
            fa0 = fmaxf(fa0, w * y0);
            float y1 = fmaf(p.x, B01, fmaf(p.y, B11, fmaf(p.z, B21, fmaf(p.w, b31, Kb1))));
            y1 = fmaxf(y1, 0.01f * y1);
            fm1 = fmaxf(fm1, y1);
            fa1 = fmaxf(fa1, w * y1);
        }
        out[n * 64 + c0] = 0.5f * (fa0 + fm0);
        out[n * 64 + c1] = 0.5f * (fa1 + fm1);

        n = n2; f = f2; wk = wk2;
    }
}

// ---------------------------------------------------------------------------
extern "C" void kernel_launch(void* const* d_in, const int* in_sizes, int n_in,
                              void* d_out, int out_size)
{
    const float4* feat  = (const float4*)d_in[0];
    const int*    np    = (const int*)   d_in[1];
    const int4*   co    = (const int4*)  d_in[2];
    const float*  W     = (const float*) d_in[3];
    const float*  gamma = (const float*) d_in[4];
    const float*  beta  = (const float*) d_in[5];
    const float*  wq    = (const float*) d_in[6];
    const float*  wk    = (const float*) d_in[7];
    const float*  wv    = (const float*) d_in[8];
    const float*  wo    = (const float*) d_in[9];
    const float*  bq    = (const float*) d_in[10];
    const float*  bk    = (const float*) d_in[11];
    const float*  bv    = (const float*) d_in[12];
    const float*  bo    = (const float*) d_in[13];
    float* out = (float*)d_out;

    pass1_kernel<<<GRID_A, 256>>>(feat, np, co, W, wq, wk, wv, wo, bq, bk, bv, bo);
    pass2_kernel<<<1, 1024>>>(W, gamma, beta);
    pass3_kernel<<<GRID_C, 256>>>(feat, W, out);
}

// round 17
// speedup vs baseline: 1.0601x; 1.0601x over previous
#include <cuda_runtime.h>

#define N_PILLARS 30000
#define WPB 8
#define GRID_A 888    // pass1: exactly 2 CTA waves at 3 CTAs/SM (888 = 2*444)
#define GRID_C 740    // pass3
#define NM_F 960000.0f
#define LOG2E 1.44269504088896340736f
#define NPART 62

__device__ float  g_w[N_PILLARS * 32];     // attention weights
__device__ float2 g_k[N_PILLARS * 32];     // per (pillar,lane) K for channels (lane, lane+32)
__device__ float  g_part[GRID_A * NPART];  // per-block stat partials
__device__ float  g_ab[128];               // [0:64)=scale a, [64:128)=bias b

#define INFF __int_as_float(0x7f800000)

__device__ __forceinline__ float wredsum(float v) {
#pragma unroll
    for (int o = 16; o; o >>= 1) v += __shfl_xor_sync(0xffffffffu, v, o);
    return v;
}
__device__ __forceinline__ float wredmax(float v) {
#pragma unroll
    for (int o = 16; o; o >>= 1) v = fmaxf(v, __shfl_xor_sync(0xffffffffu, v, o));
    return v;
}
__device__ __forceinline__ float wredmin(float v) {
#pragma unroll
    for (int o = 16; o; o >>= 1) v = fminf(v, __shfl_xor_sync(0xffffffffu, v, o));
    return v;
}
__device__ __forceinline__ float ex2a(float x) {
    float r; asm("ex2.approx.f32 %0, %1;" : "=f"(r) : "f"(x)); return r;
}

// entry e -> stage-index triple (value = st[ia]*st[ib]*st[ic])
// stage: [0..2]=cx,cy,cz  [3..5]=mx,my,mz  [6..9]=Sx,Sy,Sz,Sw  [10]=npf  [11]=1
__device__ __forceinline__ void etriple(int e, int& ia, int& ib, int& ic) {
    if (e < 3)       { ia = e; ib = 10; ic = 11; }
    else if (e < 27) { int t = e - 3; ia = t >> 2; ib = 6 + (t & 3); ic = 11; }
    else {
        int t = e - 27; int a = 0;
        while (t >= 6 - a) { t -= 6 - a; a++; }
        ia = a; ib = a + t; ic = 10;
    }
}

// ---------------------------------------------------------------------------
// Pass 1: attention -> g_w ; K -> g_k ; linearized BN stat accumulators
// (R9 champion body; only the grid changed)
// ---------------------------------------------------------------------------
__global__ __launch_bounds__(256) void pass1_kernel(
    const float4* __restrict__ feat,
    const int*    __restrict__ npts,
    const int4*   __restrict__ coors,
    const float*  __restrict__ W,
    const float*  __restrict__ wq, const float* __restrict__ wk,
    const float*  __restrict__ wv, const float* __restrict__ wo,
    const float*  __restrict__ bq, const float* __restrict__ bk,
    const float*  __restrict__ bv, const float* __restrict__ bo)
{
    __shared__ float  shw[48];
    __shared__ float4 sh_kva[WPB][32];   // {k0,v0,k1,v1}
    __shared__ float2 sh_kvb[WPB][32];   // {k2,v2}
    __shared__ float  sh_st[WPB][12];
    __shared__ float  sh_e[WPB][48];
    __shared__ float  sh_m[WPB][14];

    const int tid  = threadIdx.x;
    const int wid  = tid >> 5;
    const int lane = tid & 31;

    if (tid < 9) { shw[tid] = wq[tid]; shw[9 + tid] = wk[tid]; shw[18 + tid] = wv[tid]; shw[27 + tid] = wo[tid]; }
    if (tid < 3) { shw[36 + tid] = bq[tid]; shw[39 + tid] = bk[tid]; shw[42 + tid] = bv[tid]; shw[45 + tid] = bo[tid]; }
    __syncthreads();

    const int c0 = lane, c1 = lane + 32;
    const float P00 = W[c0] + W[448 + c0], P10 = W[64 + c0] + W[512 + c0], P20 = W[128 + c0] + W[576 + c0];
    const float Q00 = W[256 + c0], Q10 = W[320 + c0], Q20 = W[384 + c0];
    const float P01 = W[c1] + W[448 + c1], P11 = W[64 + c1] + W[512 + c1], P21 = W[128 + c1] + W[576 + c1];
    const float Q01 = W[256 + c1], Q11 = W[320 + c1], Q21 = W[384 + c1];

    int ia0, ib0, ic0, ia1, ib1, ic1;
    etriple(lane, ia0, ib0, ic0);
    const bool has1 = (lane < 16);
    etriple(has1 ? (32 + lane) : 0, ia1, ib1, ic1);

    float macc[10]; float sacc[4];
#pragma unroll
    for (int k = 0; k < 10; k++) macc[k] = 0.f;
#pragma unroll
    for (int k = 0; k < 4; k++) sacc[k] = 0.f;
    float ea0 = 0.f, ea1 = 0.f;

    for (int n = blockIdx.x * WPB + wid; n < N_PILLARS; n += GRID_A * WPB) {
        float4 f = feat[n * 32 + lane];
        int np = npts[n];
        int4 cc = coors[n];
        float cx = (float)cc.w * 0.2f + 0.1f;
        float cy = (float)cc.z * 0.2f - 39.9f;
        float cz = (float)cc.y * 4.0f - 1.0f;

        // ---- q,k,v ----
        float q0 = fmaf(f.x, shw[0], fmaf(f.y, shw[3], fmaf(f.z, shw[6], shw[36])));
        float q1 = fmaf(f.x, shw[1], fmaf(f.y, shw[4], fmaf(f.z, shw[7], shw[37])));
        float q2 = fmaf(f.x, shw[2], fmaf(f.y, shw[5], fmaf(f.z, shw[8], shw[38])));
        float k0 = fmaf(f.x, shw[9],  fmaf(f.y, shw[12], fmaf(f.z, shw[15], shw[39])));
        float k1 = fmaf(f.x, shw[10], fmaf(f.y, shw[13], fmaf(f.z, shw[16], shw[40])));
        float k2 = fmaf(f.x, shw[11], fmaf(f.y, shw[14], fmaf(f.z, shw[17], shw[41])));
        float v0 = fmaf(f.x, shw[18], fmaf(f.y, shw[21], fmaf(f.z, shw[24], shw[42])));
        float v1 = fmaf(f.x, shw[19], fmaf(f.y, shw[22], fmaf(f.z, shw[25], shw[43])));
        float v2 = fmaf(f.x, shw[20], fmaf(f.y, shw[23], fmaf(f.z, shw[26], shw[44])));
        float qs0 = q0 * LOG2E, qs1 = q1 * LOG2E, qs2 = q2 * LOG2E;

        // ---- stats reductions ----
        float Ux = wredsum(f.x), Uy = wredsum(f.y), Uz = wredsum(f.z);
        float npf = (float)np;
        float inv = __fdividef(1.0f, npf);
        float mx = Ux * inv, my = Uy * inv, mz = Uz * inv;

        bool val = (lane < np);
        float X = val ? f.x : 0.f, Y = val ? f.y : 0.f, Z = val ? f.z : 0.f, Wv = val ? f.w : 0.f;
        float Sx = wredsum(X), Sy = wredsum(Y), Sz = wredsum(Z), Sw = wredsum(Wv);

        macc[0] = fmaf(X, X, macc[0]); macc[1] = fmaf(X, Y, macc[1]);
        macc[2] = fmaf(X, Z, macc[2]); macc[3] = fmaf(X, Wv, macc[3]);
        macc[4] = fmaf(Y, Y, macc[4]); macc[5] = fmaf(Y, Z, macc[5]);
        macc[6] = fmaf(Y, Wv, macc[6]); macc[7] = fmaf(Z, Z, macc[7]);
        macc[8] = fmaf(Z, Wv, macc[8]); macc[9] = fmaf(Wv, Wv, macc[9]);
        sacc[0] += X; sacc[1] += Y; sacc[2] += Z; sacc[3] += Wv;

        float K0 = -fmaf(cx, P00, fmaf(cy, P10, fmaf(cz, P20, fmaf(mx, Q00, fmaf(my, Q10, mz * Q20)))));
        float K1 = -fmaf(cx, P01, fmaf(cy, P11, fmaf(cz, P21, fmaf(mx, Q01, fmaf(my, Q11, mz * Q21)))));
        g_k[n * 32 + lane] = make_float2(K0, K1);

        // ---- stage smem ----
        __syncwarp();
        sh_kva[wid][lane] = make_float4(k0, v0, k1, v1);
        sh_kvb[wid][lane] = make_float2(k2, v2);
        if (lane == 0) {
            float* st = sh_st[wid];
            st[0] = cx; st[1] = cy; st[2] = cz;
            st[3] = mx; st[4] = my; st[5] = mz;
            st[6] = Sx; st[7] = Sy; st[8] = Sz; st[9] = Sw;
            st[10] = npf; st[11] = 1.0f;
        }
        __syncwarp();

        const float* st = sh_st[wid];
        ea0 = fmaf(st[ia0] * st[ib0], st[ic0], ea0);
        if (has1) ea1 = fmaf(st[ia1] * st[ib1], st[ic1], ea1);

        // ---- exp loop (fully unrolled) ----
        float l0 = 0.f, l1 = 0.f, l2 = 0.f, a0 = 0.f, a1 = 0.f, a2 = 0.f;
#pragma unroll
        for (int j = 0; j < 32; j++) {
            float4 kva = sh_kva[wid][j];
            float2 kvb = sh_kvb[wid][j];
            float e0 = ex2a(qs0 * kva.x);
            float e1 = ex2a(qs1 * kva.z);
            float e2 = ex2a(qs2 * kvb.x);
            l0 += e0; l1 += e1; l2 += e2;
            a0 = fmaf(e0, kva.y, a0);
            a1 = fmaf(e1, kva.w, a1);
            a2 = fmaf(e2, kvb.y, a2);
        }
        float o0 = __fdividef(a0, l0);
        float o1 = __fdividef(a1, l1);
        float o2 = __fdividef(a2, l2);
        float t0 = fmaf(o0, shw[27], fmaf(o1, shw[30], fmaf(o2, shw[33], shw[45])));
        float t1 = fmaf(o0, shw[28], fmaf(o1, shw[31], fmaf(o2, shw[34], shw[46])));
        float t2 = fmaf(o0, shw[29], fmaf(o1, shw[32], fmaf(o2, shw[35], shw[47])));
        float ma = fmaxf(t0, fmaxf(t1, t2));
        float S = wredsum(ma);
        g_w[n * 32 + lane] = __fdividef(ma, S);
    }

    // block reduction of stats
    sh_e[wid][lane] = ea0;
    if (has1) sh_e[wid][32 + lane] = ea1;
#pragma unroll
    for (int k = 0; k < 10; k++) macc[k] = wredsum(macc[k]);
#pragma unroll
    for (int k = 0; k < 4; k++) sacc[k] = wredsum(sacc[k]);
    if (lane == 0) {
#pragma unroll
        for (int k = 0; k < 10; k++) sh_m[wid][k] = macc[k];
#pragma unroll
        for (int k = 0; k < 4; k++) sh_m[wid][10 + k] = sacc[k];
    }
    __syncthreads();
    if (tid < 48) {
        float s = 0.f;
#pragma unroll
        for (int w = 0; w < WPB; w++) s += sh_e[w][tid];
        g_part[blockIdx.x * NPART + tid] = s;
    } else if (tid < NPART) {
        float s = 0.f;
#pragma unroll
        for (int w = 0; w < WPB; w++) s += sh_m[w][tid - 48];
        g_part[blockIdx.x * NPART + tid] = s;
    }
}

// ---------------------------------------------------------------------------
// Pass 2: contract global stats per channel -> BN scale/bias
// ---------------------------------------------------------------------------
__global__ __launch_bounds__(1024) void pass2_kernel(
    const float* __restrict__ W,
    const float* __restrict__ gamma, const float* __restrict__ beta)
{
    __shared__ float shv[64][16];
    __shared__ float tot[NPART];
    int tid = threadIdx.x;
    int v = tid & 63, grp = tid >> 6;
    if (v < NPART) {
        float s = 0.f;
#pragma unroll 8
        for (int b = grp; b < GRID_A; b += 16) s += g_part[b * NPART + v];
        shv[v][grp] = s;
    }
    __syncthreads();
    if (tid < NPART) {
        float s = 0.f;
#pragma unroll
        for (int g = 0; g < 16; g++) s += shv[tid][g];
        tot[tid] = s;
    }
    __syncthreads();
    if (tid < 64) {
        int c = tid;
        float P0 = W[c] + W[448 + c], P1 = W[64 + c] + W[512 + c], P2 = W[128 + c] + W[576 + c];
        float Q0 = W[256 + c], Q1 = W[320 + c], Q2 = W[384 + c];
        float A[4] = { P0 + Q0, P1 + Q1, P2 + Q2, W[192 + c] };
        float R[6] = { P0, P1, P2, Q0, Q1, Q2 };
        float SG[4] = { tot[58], tot[59], tot[60], tot[61] };
        float T1[6] = { tot[0], tot[1], tot[2], tot[58], tot[59], tot[60] };

        float rs = A[0]*SG[0] + A[1]*SG[1] + A[2]*SG[2] + A[3]*SG[3]
                 - (R[0]*T1[0] + R[1]*T1[1] + R[2]*T1[2] + R[3]*T1[3] + R[4]*T1[4] + R[5]*T1[5]);

        float M[4][4];
        M[0][0]=tot[48]; M[0][1]=M[1][0]=tot[49]; M[0][2]=M[2][0]=tot[50]; M[0][3]=M[3][0]=tot[51];
        M[1][1]=tot[52]; M[1][2]=M[2][1]=tot[53]; M[1][3]=M[3][1]=tot[54];
        M[2][2]=tot[55]; M[2][3]=M[3][2]=tot[56]; M[3][3]=tot[57];
        float quadA = 0.f;
#pragma unroll
        for (int a = 0; a < 4; a++) {
            float h = 0.f;
#pragma unroll
            for (int b = 0; b < 4; b++) h += M[a][b] * A[b];
            quadA += A[a] * h;
        }
        float cross = 0.f;
#pragma unroll
        for (int b = 0; b < 4; b++) {
            float vb = 0.f;
#pragma unroll
            for (int a = 0; a < 6; a++) vb += R[a] * tot[3 + a * 4 + b];
            cross += vb * A[b];
        }
        float T3[6][6];
        int idx = 27;
#pragma unroll
        for (int a = 0; a < 6; a++)
#pragma unroll
            for (int b = a; b < 6; b++) { T3[a][b] = T3[b][a] = tot[idx]; idx++; }
        float quadR = 0.f;
#pragma unroll
        for (int a = 0; a < 6; a++) {
            float h = 0.f;
#pragma unroll
            for (int b = 0; b < 6; b++) h += T3[a][b] * R[b];
            quadR += R[a] * h;
        }
        float rq = quadA - 2.0f * cross + quadR;
        float mean = rs * (1.0f / NM_F);
        float var  = rq * (1.0f / NM_F) - mean * mean;
        float a = gamma[c] * rsqrtf(var + 1e-3f);
        g_ab[c] = a;
        g_ab[64 + c] = fmaf(-mean, a, beta[c]);
    }
}

// ---------------------------------------------------------------------------
// Pass 3: recompute x (K from g_k), BN folded into coefficients,
// leaky + fused fa/fm max -> out.  Software-pipelined.  (R9 exact)
// ---------------------------------------------------------------------------
__global__ __launch_bounds__(256) void pass3_kernel(
    const float4* __restrict__ feat,
    const int*    __restrict__ npts,
    const float*  __restrict__ W,
    float*        __restrict__ out)
{
    __shared__ float4 sh_p[WPB][32];
    __shared__ float  sh_wt[WPB][32];

    const int tid  = threadIdx.x;
    const int wid  = tid >> 5;
    const int lane = tid & 31;
    const int c0 = lane, c1 = lane + 32;

    const float sa0 = g_ab[c0], sb0 = g_ab[64 + c0];
    const float sa1 = g_ab[c1], sb1 = g_ab[64 + c1];

    const float B00 = sa0 * (W[c0] + W[448 + c0] + W[256 + c0]);
    const float B10 = sa0 * (W[64 + c0] + W[512 + c0] + W[320 + c0]);
    const float B20 = sa0 * (W[128 + c0] + W[576 + c0] + W[384 + c0]);
    const float b30 = sa0 * W[192 + c0];
    const float B01 = sa1 * (W[c1] + W[448 + c1] + W[256 + c1]);
    const float B11 = sa1 * (W[64 + c1] + W[512 + c1] + W[320 + c1]);
    const float B21 = sa1 * (W[128 + c1] + W[576 + c1] + W[384 + c1]);
    const float b31 = sa1 * W[192 + c1];

    const float ym0 = fmaxf(sb0, 0.01f * sb0);
    const float ym1 = fmaxf(sb1, 0.01f * sb1);

    const int stride = GRID_C * WPB;
    int n = blockIdx.x * WPB + wid;

    float4 f;  float wt;  float2 K2;  int np;
    if (n < N_PILLARS) {
        f  = feat[n * 32 + lane];
        wt = g_w[n * 32 + lane];
        K2 = g_k[n * 32 + lane];
        np = npts[n];
    }

    while (n < N_PILLARS) {
        const int n2 = n + stride;
        float4 f2; float wt2; float2 K22; int np2;
        if (n2 < N_PILLARS) {
            f2  = feat[n2 * 32 + lane];
            wt2 = g_w[n2 * 32 + lane];
            K22 = g_k[n2 * 32 + lane];
            np2 = npts[n2];
        }

        __syncwarp();
        sh_p[wid][lane]  = f;
        sh_wt[wid][lane] = wt;
        __syncwarp();

        float wmx = wredmax((lane >= np) ? wt : -INFF);
        float wmn = wredmin((lane >= np) ? wt :  INFF);

        const float Kb0 = fmaf(sa0, K2.x, sb0);
        const float Kb1 = fmaf(sa1, K2.y, sb1);

        float fm0 = -INFF, fa0 = -INFF, fm1 = -INFF, fa1 = -INFF;
        if (np < 32) {
            fm0 = ym0;  fa0 = (ym0 >= 0.f) ? ym0 * wmx : ym0 * wmn;
            fm1 = ym1;  fa1 = (ym1 >= 0.f) ? ym1 * wmx : ym1 * wmn;
        }
#pragma unroll 4
        for (int i = 0; i < np; i++) {
            float4 p = sh_p[wid][i];
            float w  = sh_wt[wid][i];
            float y0 = fmaf(p.x, B00, fmaf(p.y, B10, fmaf(p.z, B20, fmaf(p.w, b30, Kb0))));
            y0 = fmaxf(y0, 0.01f * y0);
            fm0 = fmaxf(fm0, y0);
            fa0 = fmaxf(fa0, w * y0);
            float y1 = fmaf(p.x, B01, fmaf(p.y, B11, fmaf(p.z, B21, fmaf(p.w, b31, Kb1))));
            y1 = fmaxf(y1, 0.01f * y1);
            fm1 = fmaxf(fm1, y1);
            fa1 = fmaxf(fa1, w * y1);
        }
        out[n * 64 + c0] = 0.5f * (fa0 + fm0);
        out[n * 64 + c1] = 0.5f * (fa1 + fm1);

        n = n2; f = f2; wt = wt2; K2 = K22; np = np2;
    }
}

// ---------------------------------------------------------------------------
extern "C" void kernel_launch(void* const* d_in, const int* in_sizes, int n_in,
                              void* d_out, int out_size)
{
    const float4* feat  = (const float4*)d_in[0];
    const int*    np    = (const int*)   d_in[1];
    const int4*   co    = (const int4*)  d_in[2];
    const float*  W     = (const float*) d_in[3];
    const float*  gamma = (const float*) d_in[4];
    const float*  beta  = (const float*) d_in[5];
    const float*  wq    = (const float*) d_in[6];
    const float*  wk    = (const float*) d_in[7];
    const float*  wv    = (const float*) d_in[8];
    const float*  wo    = (const float*) d_in[9];
    const float*  bq    = (const float*) d_in[10];
    const float*  bk    = (const float*) d_in[11];
    const float*  bv    = (const float*) d_in[12];
    const float*  bo    = (const float*) d_in[13];
    float* out = (float*)d_out;

    pass1_kernel<<<GRID_A, 256>>>(feat, np, co, W, wq, wk, wv, wo, bq, bk, bv, bo);
    pass2_kernel<<<1, 1024>>>(W, gamma, beta);
    pass3_kernel<<<GRID_C, 256>>>(feat, np, W, out);
}